// round 11
// baseline (speedup 1.0000x reference)
#include <cuda_runtime.h>
#include <cuda_fp16.h>
#include <cuda_fp8.h>

// Fixed problem shapes
constexpr int NN    = 50000;   // nodes
constexpr int F_IN  = 64;
constexpr int HEADS = 4;
constexpr int HID   = 32;
constexpr int C1    = HEADS * HID;  // 128
constexpr int C2    = HID;          // 32
constexpr int CLS   = 3;
constexpr int SLOTS = 96;           // bucket capacity per node (deg ~ Poisson(17))
constexpr int PB    = 64;           // partial accumulator buckets

// ---------------- scratch (device globals) ----------------------------------
__device__ __align__(16) unsigned g_h1f8[NN * (C1 / 4)];  // fp8 e4m3 layer-1 feats
__device__ __align__(16) float g_asrc1[NN * HEADS];
__device__ __align__(16) float g_adst1[NN * HEADS];
__device__ __align__(16) float g_out1[NN * C1];
__device__ __align__(16) __half g_h2h[NN * C2];           // fp16 layer-2 feats
__device__ float g_asrc2[NN];
__device__ float g_adst2[NN];
__device__ float g_paccum[PB * C2];                       // partial global sums
__device__ int   g_ei64;

// bucket CSR
__device__ int g_cursor[NN];                      // becomes degree after scatter
__device__ int g_sortbuf[NN * SLOTS];

// ---------------- init: self-loop preplacement + dtype detect ----------------
__global__ void k_init(const int* __restrict__ ei, int n) {
    int i = blockIdx.x * blockDim.x + threadIdx.x;
    int stride = gridDim.x * blockDim.x;
    for (; i < n; i += stride) {
        g_cursor[i] = 1;                 // slot 0 = self-loop
        g_sortbuf[i * SLOTS] = i;
        if (i < PB * C2) g_paccum[i] = 0.f;
    }
    if (blockIdx.x == 0 && threadIdx.x == 0) {
        int all_zero = 1;
        for (int j = 1; j < 512; j += 2)
            if (ei[j] != 0) { all_zero = 0; break; }
        g_ei64 = all_zero;
    }
}

__device__ __forceinline__ void load_edge(const int* ei, int idx, int E,
                                          int& src, int& dst) {
    if (g_ei64) {
        const long long* e64 = (const long long*)ei;
        src = (int)e64[idx];
        dst = (int)e64[E + idx];
    } else {
        src = ei[idx];
        dst = ei[E + idx];
    }
}

// ---------------- scatter into buckets (8 edges/thread for atomic ILP) ------
__global__ void k_scatter(const int* __restrict__ ei, int E) {
    int base = (blockIdx.x * blockDim.x + threadIdx.x) * 8;
    int srcs[8], dsts[8];
    #pragma unroll
    for (int u = 0; u < 8; u++) {
        int i = base + u;
        if (i < E) load_edge(ei, i, E, srcs[u], dsts[u]);
        else       dsts[u] = -1;
    }
    int pos[8];
    #pragma unroll
    for (int u = 0; u < 8; u++)
        if (dsts[u] >= 0) pos[u] = atomicAdd(&g_cursor[dsts[u]], 1);
    #pragma unroll
    for (int u = 0; u < 8; u++)
        if (dsts[u] >= 0) g_sortbuf[dsts[u] * SLOTS + pos[u]] = srcs[u];
}

// ---------------- K1: h1 = x @ W1 (fp8 store) ; attn coeffs -----------------
__global__ void __launch_bounds__(128) k_gemm1(
        const float* __restrict__ x, const float* __restrict__ W1,
        const float* __restrict__ attS, const float* __restrict__ attD, int n) {
    int t = threadIdx.x;   // output column 0..127
    float w[F_IN];
    #pragma unroll
    for (int k = 0; k < F_IN; k++) w[k] = W1[k * C1 + t];

    __shared__ float4 xsh[64 * 16];
    int n0 = blockIdx.x * 64;
    const float4* x4 = (const float4*)x;
    for (int i = t; i < 64 * 16; i += 128) {
        int node = n0 + (i >> 4);
        xsh[i] = (node < n) ? x4[node * 16 + (i & 15)] : make_float4(0.f, 0.f, 0.f, 0.f);
    }
    __syncthreads();

    float aS = attS[t], aD = attD[t];
    int lane = t & 31, wi = t >> 5;
    int nmax = min(64, n - n0);
    unsigned char* h1b = reinterpret_cast<unsigned char*>(g_h1f8);
    for (int nn = 0; nn < nmax; nn++) {
        float a0 = 0.f, a1 = 0.f, a2 = 0.f, a3 = 0.f;
        #pragma unroll
        for (int k4 = 0; k4 < 16; k4++) {
            float4 xv = xsh[nn * 16 + k4];
            a0 += xv.x * w[k4 * 4 + 0];
            a1 += xv.y * w[k4 * 4 + 1];
            a2 += xv.z * w[k4 * 4 + 2];
            a3 += xv.w * w[k4 * 4 + 3];
        }
        float acc = (a0 + a1) + (a2 + a3);
        h1b[(n0 + nn) * C1 + t] =
            (unsigned char)__nv_cvt_float_to_fp8(acc, __NV_SATFINITE, __NV_E4M3);
        float vs = acc * aS, vd = acc * aD;
        #pragma unroll
        for (int o = 16; o > 0; o >>= 1) {
            vs += __shfl_down_sync(0xffffffffu, vs, o);
            vd += __shfl_down_sync(0xffffffffu, vd, o);
        }
        if (lane == 0) {
            g_asrc1[(n0 + nn) * HEADS + wi] = vs;
            g_adst1[(n0 + nn) * HEADS + wi] = vd;
        }
    }
}

// ---------------- K2: edge pass 1, bucket CSR, warp per destination ---------
// lane owns channels [lane*4, lane*4+4) as one 4-byte fp8 load (4 sectors/edge).
__global__ void k_edge1(int n) {
    int gw = (blockIdx.x * blockDim.x + threadIdx.x) >> 5;
    if (gw >= n) return;
    int lane = threadIdx.x & 31;
    int h = lane >> 3;
    float aD = g_adst1[gw * HEADS + h];
    int start = gw * SLOTS, deg = g_cursor[gw];

    __half2 acc01 = __float2half2_rn(0.f);
    __half2 acc23 = __float2half2_rn(0.f);
    float psum = 0.f;
    for (int i = 0; i < deg; i += 32) {
        int myj = i + lane;
        int s = (myj < deg) ? g_sortbuf[start + myj] : -1;
        #pragma unroll
        for (int b = 0; b < 4; b++) {
            if (i + b * 8 < deg) {               // warp-uniform guard
                #pragma unroll
                for (int j = b * 8; j < b * 8 + 8; j++) {
                    int src = __shfl_sync(0xffffffffu, s, j);
                    if (src >= 0) {
                        float e = g_asrc1[src * HEADS + h] + aD;
                        e = fmaxf(e, 0.2f * e);
                        float p = __expf(e);
                        unsigned raw = g_h1f8[src * 32 + lane];
                        __half2_raw lo = __nv_cvt_fp8x2_to_halfraw2(
                            (__nv_fp8x2_storage_t)(raw & 0xFFFFu), __NV_E4M3);
                        __half2_raw hi = __nv_cvt_fp8x2_to_halfraw2(
                            (__nv_fp8x2_storage_t)(raw >> 16), __NV_E4M3);
                        __half2 ph = __float2half2_rn(p);
                        acc01 = __hfma2(ph, *reinterpret_cast<__half2*>(&lo), acc01);
                        acc23 = __hfma2(ph, *reinterpret_cast<__half2*>(&hi), acc23);
                        psum += p;
                    }
                }
            }
        }
    }
    float inv = 1.0f / psum;
    float2 f01 = __half22float2(acc01);
    float2 f23 = __half22float2(acc23);
    float4 o;
    o.x = f01.x * inv; o.y = f01.y * inv;
    o.z = f23.x * inv; o.w = f23.y * inv;
    reinterpret_cast<float4*>(g_out1)[gw * 32 + lane] = o;
}

// ---------------- K3: bias+ELU, GEMM2 (W2 k-chunks in regs), attn coeffs ----
__global__ void __launch_bounds__(256) k_node1(
        const float* __restrict__ W2, const float* __restrict__ b1,
        const float* __restrict__ attS2, const float* __restrict__ attD2, int n) {
    int tx = threadIdx.x;        // col 0..31
    int ty = threadIdx.y;        // k-chunk 0..7
    int t = ty * 32 + tx;

    float w2r[16];
    #pragma unroll
    for (int k = 0; k < 16; k++) w2r[k] = W2[(ty * 16 + k) * C2 + tx];

    __shared__ float hsh[16 * C1];
    __shared__ float ps[8][16][32];

    int n0 = blockIdx.x * 16;
    for (int i = t; i < 16 * C1; i += 256) {
        int nn = i >> 7, k = i & 127;
        int node = n0 + nn;
        float v = 0.f;
        if (node < n) {
            v = g_out1[node * C1 + k] + b1[k];
            v = v > 0.f ? v : expm1f(v);
        }
        hsh[i] = v;
    }
    __syncthreads();

    const float4* h4 = (const float4*)hsh;
    for (int nn = 0; nn < 16; nn++) {
        float acc = 0.f;
        #pragma unroll
        for (int k4 = 0; k4 < 4; k4++) {
            float4 hv = h4[nn * 32 + ty * 4 + k4];
            acc += hv.x * w2r[k4 * 4 + 0] + hv.y * w2r[k4 * 4 + 1]
                 + hv.z * w2r[k4 * 4 + 2] + hv.w * w2r[k4 * 4 + 3];
        }
        ps[ty][nn][tx] = acc;
    }
    __syncthreads();

    float aS = attS2[tx], aD = attD2[tx];
    #pragma unroll
    for (int pp = 0; pp < 2; pp++) {
        int nn = pp * 8 + (t >> 5);
        int col = tx;
        float s = 0.f;
        #pragma unroll
        for (int j = 0; j < 8; j++) s += ps[j][nn][col];
        int node = n0 + nn;
        float vs = s * aS, vd = s * aD;
        #pragma unroll
        for (int o = 16; o > 0; o >>= 1) {
            vs += __shfl_down_sync(0xffffffffu, vs, o);
            vd += __shfl_down_sync(0xffffffffu, vd, o);
        }
        if (node < n) {
            g_h2h[node * C2 + col] = __float2half(s);
            if (col == 0) { g_asrc2[node] = vs; g_adst2[node] = vd; }
        }
    }
}

// ---------------- K4: edge pass 2 + fused global-sum -------------------------
__global__ void k_edge2(int n) {
    __shared__ float sblock[C2];
    int t = threadIdx.x;
    if (t < C2) sblock[t] = 0.f;
    __syncthreads();

    int gw = (blockIdx.x * blockDim.x + t) >> 5;
    int lane = t & 31;
    if (gw < n) {
        int g = lane >> 3, l8 = lane & 7;
        float aD = g_adst2[gw];
        int start = gw * SLOTS, deg = g_cursor[gw];

        const uint2* h2v = reinterpret_cast<const uint2*>(g_h2h);
        float4 acc = make_float4(0.f, 0.f, 0.f, 0.f);
        float psum = 0.f;
        #pragma unroll 4
        for (int i = g; i < deg; i += 4) {
            int src = g_sortbuf[start + i];
            float e = g_asrc2[src] + aD;
            e = fmaxf(e, 0.2f * e);
            float p = __expf(e);
            uint2 raw = h2v[src * 8 + l8];
            float2 f01 = __half22float2(*reinterpret_cast<__half2*>(&raw.x));
            float2 f23 = __half22float2(*reinterpret_cast<__half2*>(&raw.y));
            acc.x += p * f01.x; acc.y += p * f01.y;
            acc.z += p * f23.x; acc.w += p * f23.y;
            psum += p;
        }
        #pragma unroll
        for (int o = 8; o <= 16; o <<= 1) {
            acc.x += __shfl_xor_sync(0xffffffffu, acc.x, o);
            acc.y += __shfl_xor_sync(0xffffffffu, acc.y, o);
            acc.z += __shfl_xor_sync(0xffffffffu, acc.z, o);
            acc.w += __shfl_xor_sync(0xffffffffu, acc.w, o);
            psum  += __shfl_xor_sync(0xffffffffu, psum,  o);
        }
        if (lane < 8) {
            float inv = 1.0f / psum;
            int c = lane * 4;
            atomicAdd(&sblock[c + 0], acc.x * inv);
            atomicAdd(&sblock[c + 1], acc.y * inv);
            atomicAdd(&sblock[c + 2], acc.z * inv);
            atomicAdd(&sblock[c + 3], acc.w * inv);
        }
    }
    __syncthreads();
    if (t < C2)
        atomicAdd(&g_paccum[(blockIdx.x & (PB - 1)) * C2 + t], sblock[t]);
}

// ---------------- K5: reduce partials -> mean -> logits -> softmax -----------
__global__ void k_out(const float* __restrict__ b2,
                      const float* __restrict__ linW, const float* __restrict__ linb,
                      float* __restrict__ out, int n) {
    __shared__ float tot[C2];
    int t = threadIdx.x;   // 32 threads
    float s = 0.f;
    for (int b = 0; b < PB; b++) s += g_paccum[b * C2 + t];
    tot[t] = s / (float)n + b2[t];
    __syncwarp();
    if (t == 0) {
        float logits[CLS];
        for (int j = 0; j < CLS; j++) {
            float acc = linb[j];
            for (int c = 0; c < C2; c++)
                acc += tot[c] * linW[c * CLS + j];
            logits[j] = acc;
        }
        float m = fmaxf(logits[0], fmaxf(logits[1], logits[2]));
        float e0 = expf(logits[0] - m);
        float e1 = expf(logits[1] - m);
        float e2 = expf(logits[2] - m);
        float sm = e0 + e1 + e2;
        out[0] = e0 / sm; out[1] = e1 / sm; out[2] = e2 / sm;
    }
}

// ---------------- launcher ---------------------------------------------------
extern "C" void kernel_launch(void* const* d_in, const int* in_sizes, int n_in,
                              void* d_out, int out_size) {
    const float* x        = (const float*)d_in[0];
    const float* W1       = (const float*)d_in[1];
    const float* att_src1 = (const float*)d_in[2];
    const float* att_dst1 = (const float*)d_in[3];
    const float* b1       = (const float*)d_in[4];
    const float* W2       = (const float*)d_in[5];
    const float* att_src2 = (const float*)d_in[6];
    const float* att_dst2 = (const float*)d_in[7];
    const float* b2       = (const float*)d_in[8];
    const float* linW     = (const float*)d_in[9];
    const float* linb     = (const float*)d_in[10];
    const int*   ei       = (const int*)d_in[11];

    int n  = in_sizes[0] / F_IN;       // 50000
    int E  = in_sizes[11] / 2;         // 800000
    float* out = (float*)d_out;

    k_init<<<64, 256>>>(ei, n);
    k_scatter<<<(E + 2047) / 2048, 256>>>(ei, E);

    k_gemm1<<<(n + 63) / 64, 128>>>(x, W1, att_src1, att_dst1, n);

    {
        long long threads = (long long)n * 32;
        k_edge1<<<(int)((threads + 255) / 256), 256>>>(n);
    }

    k_node1<<<(n + 15) / 16, dim3(32, 8)>>>(W2, b1, att_src2, att_dst2, n);

    {
        long long threads = (long long)n * 32;
        k_edge2<<<(int)((threads + 255) / 256), 256>>>(n);
    }

    k_out<<<1, 32>>>(b2, linW, linb, out, n);
}

// round 12
// speedup vs baseline: 1.0671x; 1.0671x over previous
#include <cuda_runtime.h>
#include <cuda_fp16.h>
#include <cuda_fp8.h>

// Fixed problem shapes
constexpr int NN    = 50000;   // nodes
constexpr int F_IN  = 64;
constexpr int HEADS = 4;
constexpr int HID   = 32;
constexpr int C1    = HEADS * HID;  // 128
constexpr int C2    = HID;          // 32
constexpr int CLS   = 3;
constexpr int SLOTS = 96;           // bucket capacity per node (deg ~ Poisson(17))
constexpr int PB    = 64;           // partial accumulator buckets

// ---------------- scratch (device globals) ----------------------------------
__device__ __align__(16) unsigned g_h1f8[NN * (C1 / 4)];  // fp8 e4m3 layer-1 feats
__device__ __align__(16) float g_asrc1[NN * HEADS];
__device__ __align__(16) float g_adst1[NN * HEADS];
__device__ __align__(16) float g_out1[NN * C1];
__device__ __align__(16) __half g_h2h[NN * C2];           // fp16 layer-2 feats
__device__ float g_asrc2[NN];
__device__ float g_adst2[NN];
__device__ float g_paccum[PB * C2];                       // partial global sums
__device__ int   g_ei64;

// bucket CSR
__device__ int g_cursor[NN];                      // becomes degree after scatter
__device__ int g_sortbuf[NN * SLOTS];

// ---------------- init: self-loop preplacement + dtype detect ----------------
__global__ void k_init(const int* __restrict__ ei, int n) {
    int i = blockIdx.x * blockDim.x + threadIdx.x;
    int stride = gridDim.x * blockDim.x;
    for (; i < n; i += stride) {
        g_cursor[i] = 1;                 // slot 0 = self-loop
        g_sortbuf[i * SLOTS] = i;
        if (i < PB * C2) g_paccum[i] = 0.f;
    }
    if (blockIdx.x == 0 && threadIdx.x == 0) {
        int all_zero = 1;
        for (int j = 1; j < 512; j += 2)
            if (ei[j] != 0) { all_zero = 0; break; }
        g_ei64 = all_zero;
    }
}

__device__ __forceinline__ void load_edge(const int* ei, int idx, int E,
                                          int& src, int& dst) {
    if (g_ei64) {
        const long long* e64 = (const long long*)ei;
        src = (int)e64[idx];
        dst = (int)e64[E + idx];
    } else {
        src = ei[idx];
        dst = ei[E + idx];
    }
}

// ---------------- scatter into buckets (8 edges/thread for atomic ILP) ------
__global__ void k_scatter(const int* __restrict__ ei, int E) {
    int base = (blockIdx.x * blockDim.x + threadIdx.x) * 8;
    int srcs[8], dsts[8];
    #pragma unroll
    for (int u = 0; u < 8; u++) {
        int i = base + u;
        if (i < E) load_edge(ei, i, E, srcs[u], dsts[u]);
        else       dsts[u] = -1;
    }
    int pos[8];
    #pragma unroll
    for (int u = 0; u < 8; u++)
        if (dsts[u] >= 0) pos[u] = atomicAdd(&g_cursor[dsts[u]], 1);
    #pragma unroll
    for (int u = 0; u < 8; u++)
        if (dsts[u] >= 0) g_sortbuf[dsts[u] * SLOTS + pos[u]] = srcs[u];
}

// ---------------- K1: h1 = x @ W1 (fp8 store) ; attn coeffs -----------------
__global__ void __launch_bounds__(128) k_gemm1(
        const float* __restrict__ x, const float* __restrict__ W1,
        const float* __restrict__ attS, const float* __restrict__ attD, int n) {
    int t = threadIdx.x;   // output column 0..127
    float w[F_IN];
    #pragma unroll
    for (int k = 0; k < F_IN; k++) w[k] = W1[k * C1 + t];

    __shared__ float4 xsh[64 * 16];
    int n0 = blockIdx.x * 64;
    const float4* x4 = (const float4*)x;
    for (int i = t; i < 64 * 16; i += 128) {
        int node = n0 + (i >> 4);
        xsh[i] = (node < n) ? x4[node * 16 + (i & 15)] : make_float4(0.f, 0.f, 0.f, 0.f);
    }
    __syncthreads();

    float aS = attS[t], aD = attD[t];
    int lane = t & 31, wi = t >> 5;
    int nmax = min(64, n - n0);
    unsigned char* h1b = reinterpret_cast<unsigned char*>(g_h1f8);
    for (int nn = 0; nn < nmax; nn++) {
        float a0 = 0.f, a1 = 0.f, a2 = 0.f, a3 = 0.f;
        #pragma unroll
        for (int k4 = 0; k4 < 16; k4++) {
            float4 xv = xsh[nn * 16 + k4];
            a0 += xv.x * w[k4 * 4 + 0];
            a1 += xv.y * w[k4 * 4 + 1];
            a2 += xv.z * w[k4 * 4 + 2];
            a3 += xv.w * w[k4 * 4 + 3];
        }
        float acc = (a0 + a1) + (a2 + a3);
        h1b[(n0 + nn) * C1 + t] =
            (unsigned char)__nv_cvt_float_to_fp8(acc, __NV_SATFINITE, __NV_E4M3);
        float vs = acc * aS, vd = acc * aD;
        #pragma unroll
        for (int o = 16; o > 0; o >>= 1) {
            vs += __shfl_down_sync(0xffffffffu, vs, o);
            vd += __shfl_down_sync(0xffffffffu, vd, o);
        }
        if (lane == 0) {
            g_asrc1[(n0 + nn) * HEADS + wi] = vs;
            g_adst1[(n0 + nn) * HEADS + wi] = vd;
        }
    }
}

// ---------------- K2: edge pass 1 — lane-parallel attention coefficients ----
// Phase A: lane e computes exp(leaky(asrc[src_e]+adst)) for ALL 4 heads of its
// edge (one float4 load + 4-wide exp chain), then a 16-shfl transpose parks
// p[edge][head] so the gather loop needs 1 shfl per edge.
__global__ void k_edge1(int n) {
    int gw = (blockIdx.x * blockDim.x + threadIdx.x) >> 5;
    if (gw >= n) return;
    int lane = threadIdx.x & 31;
    int h = lane >> 3;                 // my head
    int h8 = h << 3;
    const float4* asrc4 = reinterpret_cast<const float4*>(g_asrc1);
    float4 aD4 = reinterpret_cast<const float4*>(g_adst1)[gw];
    int start = gw * SLOTS, deg = g_cursor[gw];

    __half2 acc01 = __float2half2_rn(0.f);
    __half2 acc23 = __float2half2_rn(0.f);
    float psum = 0.f;

    for (int i = 0; i < deg; i += 32) {
        int myj = i + lane;
        bool valid = myj < deg;
        int s = valid ? g_sortbuf[start + myj] : 0;

        // Phase A: 4-head attention coefficients for MY edge
        float4 a4 = asrc4[s];
        float e0 = a4.x + aD4.x, e1 = a4.y + aD4.y;
        float e2 = a4.z + aD4.z, e3 = a4.w + aD4.w;
        e0 = fmaxf(e0, 0.2f * e0); e1 = fmaxf(e1, 0.2f * e1);
        e2 = fmaxf(e2, 0.2f * e2); e3 = fmaxf(e3, 0.2f * e3);
        float p0 = valid ? __expf(e0) : 0.f;
        float p1 = valid ? __expf(e1) : 0.f;
        float p2 = valid ? __expf(e2) : 0.f;
        float p3 = valid ? __expf(e3) : 0.f;

        // Transpose: pe[r] = p[edge=(lane&7)*4+r][head=h]
        float pe[4];
        #pragma unroll
        for (int r = 0; r < 4; r++) {
            int srcl = (lane & 7) * 4 + r;
            float v0 = __shfl_sync(0xffffffffu, p0, srcl);
            float v1 = __shfl_sync(0xffffffffu, p1, srcl);
            float v2 = __shfl_sync(0xffffffffu, p2, srcl);
            float v3 = __shfl_sync(0xffffffffu, p3, srcl);
            pe[r] = (h < 2) ? ((h == 0) ? v0 : v1) : ((h == 2) ? v2 : v3);
        }
        // my psum contribution: edges (lane&7)*4..+3 of head h
        psum += (pe[0] + pe[1]) + (pe[2] + pe[3]);

        // Phase B: gather + accumulate (p arrives via 1 shfl per edge)
        #pragma unroll
        for (int b = 0; b < 4; b++) {
            if (i + b * 8 < deg) {               // warp-uniform guard
                #pragma unroll
                for (int j = b * 8; j < b * 8 + 8; j++) {
                    int src = __shfl_sync(0xffffffffu, s, j);
                    float p = __shfl_sync(0xffffffffu, pe[j & 3], h8 + (j >> 2));
                    unsigned raw = g_h1f8[src * 32 + lane];
                    __half2_raw lo = __nv_cvt_fp8x2_to_halfraw2(
                        (__nv_fp8x2_storage_t)(raw & 0xFFFFu), __NV_E4M3);
                    __half2_raw hi = __nv_cvt_fp8x2_to_halfraw2(
                        (__nv_fp8x2_storage_t)(raw >> 16), __NV_E4M3);
                    __half2 ph = __float2half2_rn(p);
                    acc01 = __hfma2(ph, *reinterpret_cast<__half2*>(&lo), acc01);
                    acc23 = __hfma2(ph, *reinterpret_cast<__half2*>(&hi), acc23);
                }
            }
        }
    }

    // psum: reduce over the 8 lanes of my head (partials live lane-local)
    #pragma unroll
    for (int o = 1; o < 8; o <<= 1)
        psum += __shfl_xor_sync(0xffffffffu, psum, o);

    float inv = 1.0f / psum;
    float2 f01 = __half22float2(acc01);
    float2 f23 = __half22float2(acc23);
    float4 o;
    o.x = f01.x * inv; o.y = f01.y * inv;
    o.z = f23.x * inv; o.w = f23.y * inv;
    reinterpret_cast<float4*>(g_out1)[gw * 32 + lane] = o;
}

// ---------------- K3: bias+ELU, GEMM2 (W2 k-chunks in regs), attn coeffs ----
__global__ void __launch_bounds__(256) k_node1(
        const float* __restrict__ W2, const float* __restrict__ b1,
        const float* __restrict__ attS2, const float* __restrict__ attD2, int n) {
    int tx = threadIdx.x;        // col 0..31
    int ty = threadIdx.y;        // k-chunk 0..7
    int t = ty * 32 + tx;

    float w2r[16];
    #pragma unroll
    for (int k = 0; k < 16; k++) w2r[k] = W2[(ty * 16 + k) * C2 + tx];

    __shared__ float hsh[16 * C1];
    __shared__ float ps[8][16][32];

    int n0 = blockIdx.x * 16;
    for (int i = t; i < 16 * C1; i += 256) {
        int nn = i >> 7, k = i & 127;
        int node = n0 + nn;
        float v = 0.f;
        if (node < n) {
            v = g_out1[node * C1 + k] + b1[k];
            v = v > 0.f ? v : expm1f(v);
        }
        hsh[i] = v;
    }
    __syncthreads();

    const float4* h4 = (const float4*)hsh;
    for (int nn = 0; nn < 16; nn++) {
        float acc = 0.f;
        #pragma unroll
        for (int k4 = 0; k4 < 4; k4++) {
            float4 hv = h4[nn * 32 + ty * 4 + k4];
            acc += hv.x * w2r[k4 * 4 + 0] + hv.y * w2r[k4 * 4 + 1]
                 + hv.z * w2r[k4 * 4 + 2] + hv.w * w2r[k4 * 4 + 3];
        }
        ps[ty][nn][tx] = acc;
    }
    __syncthreads();

    float aS = attS2[tx], aD = attD2[tx];
    #pragma unroll
    for (int pp = 0; pp < 2; pp++) {
        int nn = pp * 8 + (t >> 5);
        int col = tx;
        float s = 0.f;
        #pragma unroll
        for (int j = 0; j < 8; j++) s += ps[j][nn][col];
        int node = n0 + nn;
        float vs = s * aS, vd = s * aD;
        #pragma unroll
        for (int o = 16; o > 0; o >>= 1) {
            vs += __shfl_down_sync(0xffffffffu, vs, o);
            vd += __shfl_down_sync(0xffffffffu, vd, o);
        }
        if (node < n) {
            g_h2h[node * C2 + col] = __float2half(s);
            if (col == 0) { g_asrc2[node] = vs; g_adst2[node] = vd; }
        }
    }
}

// ---------------- K4: edge pass 2 + fused global-sum -------------------------
__global__ void k_edge2(int n) {
    __shared__ float sblock[C2];
    int t = threadIdx.x;
    if (t < C2) sblock[t] = 0.f;
    __syncthreads();

    int gw = (blockIdx.x * blockDim.x + t) >> 5;
    int lane = t & 31;
    if (gw < n) {
        int g = lane >> 3, l8 = lane & 7;
        float aD = g_adst2[gw];
        int start = gw * SLOTS, deg = g_cursor[gw];

        const uint2* h2v = reinterpret_cast<const uint2*>(g_h2h);
        float4 acc = make_float4(0.f, 0.f, 0.f, 0.f);
        float psum = 0.f;
        #pragma unroll 4
        for (int i = g; i < deg; i += 4) {
            int src = g_sortbuf[start + i];
            float e = g_asrc2[src] + aD;
            e = fmaxf(e, 0.2f * e);
            float p = __expf(e);
            uint2 raw = h2v[src * 8 + l8];
            float2 f01 = __half22float2(*reinterpret_cast<__half2*>(&raw.x));
            float2 f23 = __half22float2(*reinterpret_cast<__half2*>(&raw.y));
            acc.x += p * f01.x; acc.y += p * f01.y;
            acc.z += p * f23.x; acc.w += p * f23.y;
            psum += p;
        }
        #pragma unroll
        for (int o = 8; o <= 16; o <<= 1) {
            acc.x += __shfl_xor_sync(0xffffffffu, acc.x, o);
            acc.y += __shfl_xor_sync(0xffffffffu, acc.y, o);
            acc.z += __shfl_xor_sync(0xffffffffu, acc.z, o);
            acc.w += __shfl_xor_sync(0xffffffffu, acc.w, o);
            psum  += __shfl_xor_sync(0xffffffffu, psum,  o);
        }
        if (lane < 8) {
            float inv = 1.0f / psum;
            int c = lane * 4;
            atomicAdd(&sblock[c + 0], acc.x * inv);
            atomicAdd(&sblock[c + 1], acc.y * inv);
            atomicAdd(&sblock[c + 2], acc.z * inv);
            atomicAdd(&sblock[c + 3], acc.w * inv);
        }
    }
    __syncthreads();
    if (t < C2)
        atomicAdd(&g_paccum[(blockIdx.x & (PB - 1)) * C2 + t], sblock[t]);
}

// ---------------- K5: reduce partials -> mean -> logits -> softmax -----------
__global__ void k_out(const float* __restrict__ b2,
                      const float* __restrict__ linW, const float* __restrict__ linb,
                      float* __restrict__ out, int n) {
    __shared__ float tot[C2];
    int t = threadIdx.x;   // 32 threads
    float s = 0.f;
    for (int b = 0; b < PB; b++) s += g_paccum[b * C2 + t];
    tot[t] = s / (float)n + b2[t];
    __syncwarp();
    if (t == 0) {
        float logits[CLS];
        for (int j = 0; j < CLS; j++) {
            float acc = linb[j];
            for (int c = 0; c < C2; c++)
                acc += tot[c] * linW[c * CLS + j];
            logits[j] = acc;
        }
        float m = fmaxf(logits[0], fmaxf(logits[1], logits[2]));
        float e0 = expf(logits[0] - m);
        float e1 = expf(logits[1] - m);
        float e2 = expf(logits[2] - m);
        float sm = e0 + e1 + e2;
        out[0] = e0 / sm; out[1] = e1 / sm; out[2] = e2 / sm;
    }
}

// ---------------- launcher ---------------------------------------------------
extern "C" void kernel_launch(void* const* d_in, const int* in_sizes, int n_in,
                              void* d_out, int out_size) {
    const float* x        = (const float*)d_in[0];
    const float* W1       = (const float*)d_in[1];
    const float* att_src1 = (const float*)d_in[2];
    const float* att_dst1 = (const float*)d_in[3];
    const float* b1       = (const float*)d_in[4];
    const float* W2       = (const float*)d_in[5];
    const float* att_src2 = (const float*)d_in[6];
    const float* att_dst2 = (const float*)d_in[7];
    const float* b2       = (const float*)d_in[8];
    const float* linW     = (const float*)d_in[9];
    const float* linb     = (const float*)d_in[10];
    const int*   ei       = (const int*)d_in[11];

    int n  = in_sizes[0] / F_IN;       // 50000
    int E  = in_sizes[11] / 2;         // 800000
    float* out = (float*)d_out;

    k_init<<<64, 256>>>(ei, n);
    k_scatter<<<(E + 2047) / 2048, 256>>>(ei, E);

    k_gemm1<<<(n + 63) / 64, 128>>>(x, W1, att_src1, att_dst1, n);

    {
        long long threads = (long long)n * 32;
        k_edge1<<<(int)((threads + 255) / 256), 256>>>(n);
    }

    k_node1<<<(n + 15) / 16, dim3(32, 8)>>>(W2, b1, att_src2, att_dst2, n);

    {
        long long threads = (long long)n * 32;
        k_edge2<<<(int)((threads + 255) / 256), 256>>>(n);
    }

    k_out<<<1, 32>>>(b2, linW, linb, out, n);
}

// round 13
// speedup vs baseline: 1.1473x; 1.0751x over previous
#include <cuda_runtime.h>
#include <cuda_fp16.h>
#include <cuda_fp8.h>

// Fixed problem shapes
constexpr int NN    = 50000;   // nodes
constexpr int F_IN  = 64;
constexpr int HEADS = 4;
constexpr int HID   = 32;
constexpr int C1    = HEADS * HID;  // 128
constexpr int C2    = HID;          // 32
constexpr int CLS   = 3;
constexpr int SLOTS = 96;           // bucket capacity per node (deg ~ Poisson(17))
constexpr int PB    = 64;           // partial accumulator buckets

// ---------------- scratch (device globals) ----------------------------------
__device__ __align__(16) unsigned g_h1f8[NN * (C1 / 4)];  // fp8 e4m3 layer-1 feats
__device__ __align__(16) float g_asrc1[NN * HEADS];
__device__ __align__(16) float g_adst1[NN * HEADS];
__device__ __align__(16) float g_out1[NN * C1];
__device__ __align__(16) __half g_h2h[NN * C2];           // fp16 layer-2 feats
__device__ float g_asrc2[NN];
__device__ float g_adst2[NN];
__device__ float g_paccum[PB * C2];                       // partial global sums
__device__ int   g_ei64;

// bucket CSR
__device__ int g_cursor[NN];                      // becomes degree after scatter
__device__ int g_sortbuf[NN * SLOTS];

// ---------------- init: self-loop preplacement + dtype detect ----------------
__global__ void k_init(const int* __restrict__ ei, int n) {
    int i = blockIdx.x * blockDim.x + threadIdx.x;
    int stride = gridDim.x * blockDim.x;
    for (; i < n; i += stride) {
        g_cursor[i] = 1;                 // slot 0 = self-loop
        g_sortbuf[i * SLOTS] = i;
        if (i < PB * C2) g_paccum[i] = 0.f;
    }
    if (blockIdx.x == 0 && threadIdx.x == 0) {
        int all_zero = 1;
        for (int j = 1; j < 512; j += 2)
            if (ei[j] != 0) { all_zero = 0; break; }
        g_ei64 = all_zero;
    }
}

__device__ __forceinline__ void load_edge(const int* ei, int idx, int E,
                                          int& src, int& dst) {
    if (g_ei64) {
        const long long* e64 = (const long long*)ei;
        src = (int)e64[idx];
        dst = (int)e64[E + idx];
    } else {
        src = ei[idx];
        dst = ei[E + idx];
    }
}

// ---------------- FUSED: gemm1 blocks || scatter blocks ----------------------
// Blocks [0, nGemm): h1 = x @ W1 (fp8 store) + attention coefficients.
// Blocks [nGemm, ...): bucket-CSR scatter (8 edges/thread, atomic ILP).
// Independent inputs; both only need k_init. Co-residency overlaps the
// atomic-latency-bound scatter with the issue-bound GEMM.
__global__ void __launch_bounds__(128) k_gemm1_scatter(
        const float* __restrict__ x, const float* __restrict__ W1,
        const float* __restrict__ attS, const float* __restrict__ attD,
        const int* __restrict__ ei, int n, int E, int nGemm) {
    if ((int)blockIdx.x >= nGemm) {
        // ---------------- scatter part ----------------
        int sb = blockIdx.x - nGemm;
        int base = (sb * 128 + threadIdx.x) * 8;
        int srcs[8], dsts[8];
        #pragma unroll
        for (int u = 0; u < 8; u++) {
            int i = base + u;
            if (i < E) load_edge(ei, i, E, srcs[u], dsts[u]);
            else       dsts[u] = -1;
        }
        int pos[8];
        #pragma unroll
        for (int u = 0; u < 8; u++)
            if (dsts[u] >= 0) pos[u] = atomicAdd(&g_cursor[dsts[u]], 1);
        #pragma unroll
        for (int u = 0; u < 8; u++)
            if (dsts[u] >= 0) g_sortbuf[dsts[u] * SLOTS + pos[u]] = srcs[u];
        return;
    }

    // ---------------- gemm part ----------------
    __shared__ float4 xsh[64 * 16];
    int t = threadIdx.x;   // output column 0..127
    float w[F_IN];
    #pragma unroll
    for (int k = 0; k < F_IN; k++) w[k] = W1[k * C1 + t];

    int n0 = blockIdx.x * 64;
    const float4* x4 = (const float4*)x;
    for (int i = t; i < 64 * 16; i += 128) {
        int node = n0 + (i >> 4);
        xsh[i] = (node < n) ? x4[node * 16 + (i & 15)] : make_float4(0.f, 0.f, 0.f, 0.f);
    }
    __syncthreads();

    float aS = attS[t], aD = attD[t];
    int lane = t & 31, wi = t >> 5;
    int nmax = min(64, n - n0);
    unsigned char* h1b = reinterpret_cast<unsigned char*>(g_h1f8);
    for (int nn = 0; nn < nmax; nn++) {
        float a0 = 0.f, a1 = 0.f, a2 = 0.f, a3 = 0.f;
        #pragma unroll
        for (int k4 = 0; k4 < 16; k4++) {
            float4 xv = xsh[nn * 16 + k4];
            a0 += xv.x * w[k4 * 4 + 0];
            a1 += xv.y * w[k4 * 4 + 1];
            a2 += xv.z * w[k4 * 4 + 2];
            a3 += xv.w * w[k4 * 4 + 3];
        }
        float acc = (a0 + a1) + (a2 + a3);
        h1b[(n0 + nn) * C1 + t] =
            (unsigned char)__nv_cvt_float_to_fp8(acc, __NV_SATFINITE, __NV_E4M3);
        float vs = acc * aS, vd = acc * aD;
        #pragma unroll
        for (int o = 16; o > 0; o >>= 1) {
            vs += __shfl_down_sync(0xffffffffu, vs, o);
            vd += __shfl_down_sync(0xffffffffu, vd, o);
        }
        if (lane == 0) {
            g_asrc1[(n0 + nn) * HEADS + wi] = vs;
            g_adst1[(n0 + nn) * HEADS + wi] = vd;
        }
    }
}

// ---------------- K2: edge pass 1 — lane-parallel attention coefficients ----
__global__ void k_edge1(int n) {
    int gw = (blockIdx.x * blockDim.x + threadIdx.x) >> 5;
    if (gw >= n) return;
    int lane = threadIdx.x & 31;
    int h = lane >> 3;                 // my head
    int h8 = h << 3;
    const float4* asrc4 = reinterpret_cast<const float4*>(g_asrc1);
    float4 aD4 = reinterpret_cast<const float4*>(g_adst1)[gw];
    int start = gw * SLOTS, deg = g_cursor[gw];

    __half2 acc01 = __float2half2_rn(0.f);
    __half2 acc23 = __float2half2_rn(0.f);
    float psum = 0.f;

    for (int i = 0; i < deg; i += 32) {
        int myj = i + lane;
        bool valid = myj < deg;
        int s = valid ? g_sortbuf[start + myj] : 0;

        // Phase A: 4-head attention coefficients for MY edge
        float4 a4 = asrc4[s];
        float e0 = a4.x + aD4.x, e1 = a4.y + aD4.y;
        float e2 = a4.z + aD4.z, e3 = a4.w + aD4.w;
        e0 = fmaxf(e0, 0.2f * e0); e1 = fmaxf(e1, 0.2f * e1);
        e2 = fmaxf(e2, 0.2f * e2); e3 = fmaxf(e3, 0.2f * e3);
        float p0 = valid ? __expf(e0) : 0.f;
        float p1 = valid ? __expf(e1) : 0.f;
        float p2 = valid ? __expf(e2) : 0.f;
        float p3 = valid ? __expf(e3) : 0.f;

        // Transpose: pe[r] = p[edge=(lane&7)*4+r][head=h]
        float pe[4];
        #pragma unroll
        for (int r = 0; r < 4; r++) {
            int srcl = (lane & 7) * 4 + r;
            float v0 = __shfl_sync(0xffffffffu, p0, srcl);
            float v1 = __shfl_sync(0xffffffffu, p1, srcl);
            float v2 = __shfl_sync(0xffffffffu, p2, srcl);
            float v3 = __shfl_sync(0xffffffffu, p3, srcl);
            pe[r] = (h < 2) ? ((h == 0) ? v0 : v1) : ((h == 2) ? v2 : v3);
        }
        psum += (pe[0] + pe[1]) + (pe[2] + pe[3]);

        // Phase B: gather + accumulate (p arrives via 1 shfl per edge)
        #pragma unroll
        for (int b = 0; b < 4; b++) {
            if (i + b * 8 < deg) {               // warp-uniform guard
                #pragma unroll
                for (int j = b * 8; j < b * 8 + 8; j++) {
                    int src = __shfl_sync(0xffffffffu, s, j);
                    float p = __shfl_sync(0xffffffffu, pe[j & 3], h8 + (j >> 2));
                    unsigned raw = g_h1f8[src * 32 + lane];
                    __half2_raw lo = __nv_cvt_fp8x2_to_halfraw2(
                        (__nv_fp8x2_storage_t)(raw & 0xFFFFu), __NV_E4M3);
                    __half2_raw hi = __nv_cvt_fp8x2_to_halfraw2(
                        (__nv_fp8x2_storage_t)(raw >> 16), __NV_E4M3);
                    __half2 ph = __float2half2_rn(p);
                    acc01 = __hfma2(ph, *reinterpret_cast<__half2*>(&lo), acc01);
                    acc23 = __hfma2(ph, *reinterpret_cast<__half2*>(&hi), acc23);
                }
            }
        }
    }

    #pragma unroll
    for (int o = 1; o < 8; o <<= 1)
        psum += __shfl_xor_sync(0xffffffffu, psum, o);

    float inv = 1.0f / psum;
    float2 f01 = __half22float2(acc01);
    float2 f23 = __half22float2(acc23);
    float4 o;
    o.x = f01.x * inv; o.y = f01.y * inv;
    o.z = f23.x * inv; o.w = f23.y * inv;
    reinterpret_cast<float4*>(g_out1)[gw * 32 + lane] = o;
}

// ---------------- K3: bias+ELU, GEMM2 (W2 k-chunks in regs), attn coeffs ----
__global__ void __launch_bounds__(256) k_node1(
        const float* __restrict__ W2, const float* __restrict__ b1,
        const float* __restrict__ attS2, const float* __restrict__ attD2, int n) {
    int tx = threadIdx.x;        // col 0..31
    int ty = threadIdx.y;        // k-chunk 0..7
    int t = ty * 32 + tx;

    float w2r[16];
    #pragma unroll
    for (int k = 0; k < 16; k++) w2r[k] = W2[(ty * 16 + k) * C2 + tx];

    __shared__ float hsh[16 * C1];
    __shared__ float ps[8][16][32];

    int n0 = blockIdx.x * 16;
    for (int i = t; i < 16 * C1; i += 256) {
        int nn = i >> 7, k = i & 127;
        int node = n0 + nn;
        float v = 0.f;
        if (node < n) {
            v = g_out1[node * C1 + k] + b1[k];
            v = v > 0.f ? v : expm1f(v);
        }
        hsh[i] = v;
    }
    __syncthreads();

    const float4* h4 = (const float4*)hsh;
    for (int nn = 0; nn < 16; nn++) {
        float acc = 0.f;
        #pragma unroll
        for (int k4 = 0; k4 < 4; k4++) {
            float4 hv = h4[nn * 32 + ty * 4 + k4];
            acc += hv.x * w2r[k4 * 4 + 0] + hv.y * w2r[k4 * 4 + 1]
                 + hv.z * w2r[k4 * 4 + 2] + hv.w * w2r[k4 * 4 + 3];
        }
        ps[ty][nn][tx] = acc;
    }
    __syncthreads();

    float aS = attS2[tx], aD = attD2[tx];
    #pragma unroll
    for (int pp = 0; pp < 2; pp++) {
        int nn = pp * 8 + (t >> 5);
        int col = tx;
        float s = 0.f;
        #pragma unroll
        for (int j = 0; j < 8; j++) s += ps[j][nn][col];
        int node = n0 + nn;
        float vs = s * aS, vd = s * aD;
        #pragma unroll
        for (int o = 16; o > 0; o >>= 1) {
            vs += __shfl_down_sync(0xffffffffu, vs, o);
            vd += __shfl_down_sync(0xffffffffu, vd, o);
        }
        if (node < n) {
            g_h2h[node * C2 + col] = __float2half(s);
            if (col == 0) { g_asrc2[node] = vs; g_adst2[node] = vd; }
        }
    }
}

// ---------------- K4: edge pass 2 + fused global-sum -------------------------
__global__ void k_edge2(int n) {
    __shared__ float sblock[C2];
    int t = threadIdx.x;
    if (t < C2) sblock[t] = 0.f;
    __syncthreads();

    int gw = (blockIdx.x * blockDim.x + t) >> 5;
    int lane = t & 31;
    if (gw < n) {
        int g = lane >> 3, l8 = lane & 7;
        float aD = g_adst2[gw];
        int start = gw * SLOTS, deg = g_cursor[gw];

        const uint2* h2v = reinterpret_cast<const uint2*>(g_h2h);
        float4 acc = make_float4(0.f, 0.f, 0.f, 0.f);
        float psum = 0.f;
        #pragma unroll 4
        for (int i = g; i < deg; i += 4) {
            int src = g_sortbuf[start + i];
            float e = g_asrc2[src] + aD;
            e = fmaxf(e, 0.2f * e);
            float p = __expf(e);
            uint2 raw = h2v[src * 8 + l8];
            float2 f01 = __half22float2(*reinterpret_cast<__half2*>(&raw.x));
            float2 f23 = __half22float2(*reinterpret_cast<__half2*>(&raw.y));
            acc.x += p * f01.x; acc.y += p * f01.y;
            acc.z += p * f23.x; acc.w += p * f23.y;
            psum += p;
        }
        #pragma unroll
        for (int o = 8; o <= 16; o <<= 1) {
            acc.x += __shfl_xor_sync(0xffffffffu, acc.x, o);
            acc.y += __shfl_xor_sync(0xffffffffu, acc.y, o);
            acc.z += __shfl_xor_sync(0xffffffffu, acc.z, o);
            acc.w += __shfl_xor_sync(0xffffffffu, acc.w, o);
            psum  += __shfl_xor_sync(0xffffffffu, psum,  o);
        }
        if (lane < 8) {
            float inv = 1.0f / psum;
            int c = lane * 4;
            atomicAdd(&sblock[c + 0], acc.x * inv);
            atomicAdd(&sblock[c + 1], acc.y * inv);
            atomicAdd(&sblock[c + 2], acc.z * inv);
            atomicAdd(&sblock[c + 3], acc.w * inv);
        }
    }
    __syncthreads();
    if (t < C2)
        atomicAdd(&g_paccum[(blockIdx.x & (PB - 1)) * C2 + t], sblock[t]);
}

// ---------------- K5: reduce partials -> mean -> logits -> softmax -----------
// 128 threads: col = t&31, quarter = t>>5 sums 16 partial buckets.
__global__ void k_out(const float* __restrict__ b2,
                      const float* __restrict__ linW, const float* __restrict__ linb,
                      float* __restrict__ out, int n) {
    __shared__ float part[4][C2];
    __shared__ float tot[C2];
    int t = threadIdx.x;
    int c = t & 31, q = t >> 5;
    float s = 0.f;
    #pragma unroll
    for (int b = 0; b < PB / 4; b++)
        s += g_paccum[(q * (PB / 4) + b) * C2 + c];
    part[q][c] = s;
    __syncthreads();
    if (t < C2) {
        float v = (part[0][t] + part[1][t]) + (part[2][t] + part[3][t]);
        tot[t] = v / (float)n + b2[t];
    }
    __syncthreads();
    if (t == 0) {
        float logits[CLS];
        for (int j = 0; j < CLS; j++) {
            float acc = linb[j];
            for (int cc = 0; cc < C2; cc++)
                acc += tot[cc] * linW[cc * CLS + j];
            logits[j] = acc;
        }
        float m = fmaxf(logits[0], fmaxf(logits[1], logits[2]));
        float e0 = expf(logits[0] - m);
        float e1 = expf(logits[1] - m);
        float e2 = expf(logits[2] - m);
        float sm = e0 + e1 + e2;
        out[0] = e0 / sm; out[1] = e1 / sm; out[2] = e2 / sm;
    }
}

// ---------------- launcher ---------------------------------------------------
extern "C" void kernel_launch(void* const* d_in, const int* in_sizes, int n_in,
                              void* d_out, int out_size) {
    const float* x        = (const float*)d_in[0];
    const float* W1       = (const float*)d_in[1];
    const float* att_src1 = (const float*)d_in[2];
    const float* att_dst1 = (const float*)d_in[3];
    const float* b1       = (const float*)d_in[4];
    const float* W2       = (const float*)d_in[5];
    const float* att_src2 = (const float*)d_in[6];
    const float* att_dst2 = (const float*)d_in[7];
    const float* b2       = (const float*)d_in[8];
    const float* linW     = (const float*)d_in[9];
    const float* linb     = (const float*)d_in[10];
    const int*   ei       = (const int*)d_in[11];

    int n  = in_sizes[0] / F_IN;       // 50000
    int E  = in_sizes[11] / 2;         // 800000
    float* out = (float*)d_out;

    k_init<<<64, 256>>>(ei, n);

    int nGemm = (n + 63) / 64;                   // 782
    int nScat = (E + 1023) / 1024;               // 782 (128 thr x 8 edges)
    k_gemm1_scatter<<<nGemm + nScat, 128>>>(x, W1, att_src1, att_dst1,
                                            ei, n, E, nGemm);

    {
        long long threads = (long long)n * 32;
        k_edge1<<<(int)((threads + 255) / 256), 256>>>(n);
    }

    k_node1<<<(n + 15) / 16, dim3(32, 8)>>>(W2, b1, att_src2, att_dst2, n);

    {
        long long threads = (long long)n * 32;
        k_edge2<<<(int)((threads + 255) / 256), 256>>>(n);
    }

    k_out<<<1, 128>>>(b2, linW, linb, out, n);
}

// round 14
// speedup vs baseline: 1.2475x; 1.0874x over previous
#include <cuda_runtime.h>
#include <cuda_fp16.h>
#include <cuda_fp8.h>

// Fixed problem shapes
constexpr int NN    = 50000;   // nodes
constexpr int F_IN  = 64;
constexpr int HEADS = 4;
constexpr int HID   = 32;
constexpr int C1    = HEADS * HID;  // 128
constexpr int C2    = HID;          // 32
constexpr int CLS   = 3;
constexpr int SLOTS = 96;           // bucket capacity (in-deg ~ Poisson(16))
constexpr int PB    = 64;           // partial accumulator buckets

// ---------------- scratch (device globals; zero-init at module load) --------
// Invariant maintained across graph replays: g_cursor == 0 (reset by k_edge2),
// g_paccum == 0 (reset by k_out). Self-loops are handled in-register.
__device__ __align__(16) unsigned g_h1f8[NN * (C1 / 4)];  // fp8 e4m3 layer-1 feats
__device__ __align__(16) float g_asrc1[NN * HEADS];
__device__ __align__(16) float g_adst1[NN * HEADS];
__device__ __align__(16) float g_out1[NN * C1];
__device__ __align__(16) __half g_h2h[NN * C2];           // fp16 layer-2 feats
__device__ float g_asrc2[NN];
__device__ float g_adst2[NN];
__device__ float g_paccum[PB * C2];
__device__ int g_cursor[NN];                      // in-degree after scatter
__device__ int g_sortbuf[NN * SLOTS];

__device__ __forceinline__ void load_edge(const int* ei, int idx, int E,
                                          int e64, int& src, int& dst) {
    if (e64) {
        const long long* p = (const long long*)ei;
        src = (int)p[idx];
        dst = (int)p[E + idx];
    } else {
        src = ei[idx];
        dst = ei[E + idx];
    }
}

// ---------------- FUSED: gemm1 blocks || scatter blocks ----------------------
__global__ void __launch_bounds__(128) k_gemm1_scatter(
        const float* __restrict__ x, const float* __restrict__ W1,
        const float* __restrict__ attS, const float* __restrict__ attD,
        const int* __restrict__ ei, int n, int E, int nGemm) {
    if ((int)blockIdx.x >= nGemm) {
        // ---------------- scatter part ----------------
        __shared__ int s_e64;
        if (threadIdx.x < 32) {
            // int64 edge_index => high words (odd int32 slots) all zero.
            int sample = (threadIdx.x < 16) ? ei[threadIdx.x * 2 + 1] : 0;
            int all0 = __all_sync(0xffffffffu, sample == 0);
            if (threadIdx.x == 0) s_e64 = all0;
        }
        __syncthreads();
        int e64 = s_e64;

        int sb = blockIdx.x - nGemm;
        int base = (sb * 128 + threadIdx.x) * 8;
        int srcs[8], dsts[8];
        #pragma unroll
        for (int u = 0; u < 8; u++) {
            int i = base + u;
            if (i < E) load_edge(ei, i, E, e64, srcs[u], dsts[u]);
            else       dsts[u] = -1;
        }
        int pos[8];
        #pragma unroll
        for (int u = 0; u < 8; u++)
            if (dsts[u] >= 0) pos[u] = atomicAdd(&g_cursor[dsts[u]], 1);
        #pragma unroll
        for (int u = 0; u < 8; u++)
            if (dsts[u] >= 0) g_sortbuf[dsts[u] * SLOTS + pos[u]] = srcs[u];
        return;
    }

    // ---------------- gemm part ----------------
    __shared__ float4 xsh[64 * 16];
    int t = threadIdx.x;   // output column 0..127
    float w[F_IN];
    #pragma unroll
    for (int k = 0; k < F_IN; k++) w[k] = W1[k * C1 + t];

    int n0 = blockIdx.x * 64;
    const float4* x4 = (const float4*)x;
    for (int i = t; i < 64 * 16; i += 128) {
        int node = n0 + (i >> 4);
        xsh[i] = (node < n) ? x4[node * 16 + (i & 15)] : make_float4(0.f, 0.f, 0.f, 0.f);
    }
    __syncthreads();

    float aS = attS[t], aD = attD[t];
    int lane = t & 31, wi = t >> 5;
    int nmax = min(64, n - n0);
    unsigned char* h1b = reinterpret_cast<unsigned char*>(g_h1f8);
    for (int nn = 0; nn < nmax; nn++) {
        float a0 = 0.f, a1 = 0.f, a2 = 0.f, a3 = 0.f;
        #pragma unroll
        for (int k4 = 0; k4 < 16; k4++) {
            float4 xv = xsh[nn * 16 + k4];
            a0 += xv.x * w[k4 * 4 + 0];
            a1 += xv.y * w[k4 * 4 + 1];
            a2 += xv.z * w[k4 * 4 + 2];
            a3 += xv.w * w[k4 * 4 + 3];
        }
        float acc = (a0 + a1) + (a2 + a3);
        h1b[(n0 + nn) * C1 + t] =
            (unsigned char)__nv_cvt_float_to_fp8(acc, __NV_SATFINITE, __NV_E4M3);
        float vs = acc * aS, vd = acc * aD;
        #pragma unroll
        for (int o = 16; o > 0; o >>= 1) {
            vs += __shfl_down_sync(0xffffffffu, vs, o);
            vd += __shfl_down_sync(0xffffffffu, vd, o);
        }
        if (lane == 0) {
            g_asrc1[(n0 + nn) * HEADS + wi] = vs;
            g_adst1[(n0 + nn) * HEADS + wi] = vd;
        }
    }
}

// ---------------- K2: edge pass 1 — lane-parallel attn, self-loop in-reg ----
__global__ void k_edge1(int n) {
    int gw = (blockIdx.x * blockDim.x + threadIdx.x) >> 5;
    if (gw >= n) return;
    int lane = threadIdx.x & 31;
    int h = lane >> 3;                 // my head
    int h8 = h << 3;
    const float4* asrc4 = reinterpret_cast<const float4*>(g_asrc1);
    float4 aD4 = reinterpret_cast<const float4*>(g_adst1)[gw];
    int start = gw * SLOTS, deg = g_cursor[gw];

    __half2 acc01 = __float2half2_rn(0.f);
    __half2 acc23 = __float2half2_rn(0.f);
    float psum = 0.f;

    // self-loop (in-register)
    {
        float4 a4 = asrc4[gw];
        float e0 = a4.x + aD4.x, e1 = a4.y + aD4.y;
        float e2 = a4.z + aD4.z, e3 = a4.w + aD4.w;
        e0 = fmaxf(e0, 0.2f * e0); e1 = fmaxf(e1, 0.2f * e1);
        e2 = fmaxf(e2, 0.2f * e2); e3 = fmaxf(e3, 0.2f * e3);
        float eh = (h < 2) ? ((h == 0) ? e0 : e1) : ((h == 2) ? e2 : e3);
        float pS = __expf(eh);
        if ((lane & 7) == 0) psum += pS;     // counted once per 8-lane head group
        unsigned raw = g_h1f8[gw * 32 + lane];
        __half2_raw lo = __nv_cvt_fp8x2_to_halfraw2(
            (__nv_fp8x2_storage_t)(raw & 0xFFFFu), __NV_E4M3);
        __half2_raw hi = __nv_cvt_fp8x2_to_halfraw2(
            (__nv_fp8x2_storage_t)(raw >> 16), __NV_E4M3);
        __half2 ph = __float2half2_rn(pS);
        acc01 = __hfma2(ph, *reinterpret_cast<__half2*>(&lo), acc01);
        acc23 = __hfma2(ph, *reinterpret_cast<__half2*>(&hi), acc23);
    }

    for (int i = 0; i < deg; i += 32) {
        int myj = i + lane;
        bool valid = myj < deg;
        int s = valid ? g_sortbuf[start + myj] : 0;

        // Phase A: 4-head attention coefficients for MY edge
        float4 a4 = asrc4[s];
        float e0 = a4.x + aD4.x, e1 = a4.y + aD4.y;
        float e2 = a4.z + aD4.z, e3 = a4.w + aD4.w;
        e0 = fmaxf(e0, 0.2f * e0); e1 = fmaxf(e1, 0.2f * e1);
        e2 = fmaxf(e2, 0.2f * e2); e3 = fmaxf(e3, 0.2f * e3);
        float p0 = valid ? __expf(e0) : 0.f;
        float p1 = valid ? __expf(e1) : 0.f;
        float p2 = valid ? __expf(e2) : 0.f;
        float p3 = valid ? __expf(e3) : 0.f;

        // Transpose: pe[r] = p[edge=(lane&7)*4+r][head=h]
        float pe[4];
        #pragma unroll
        for (int r = 0; r < 4; r++) {
            int srcl = (lane & 7) * 4 + r;
            float v0 = __shfl_sync(0xffffffffu, p0, srcl);
            float v1 = __shfl_sync(0xffffffffu, p1, srcl);
            float v2 = __shfl_sync(0xffffffffu, p2, srcl);
            float v3 = __shfl_sync(0xffffffffu, p3, srcl);
            pe[r] = (h < 2) ? ((h == 0) ? v0 : v1) : ((h == 2) ? v2 : v3);
        }
        psum += (pe[0] + pe[1]) + (pe[2] + pe[3]);

        // Phase B: gather + accumulate
        #pragma unroll
        for (int b = 0; b < 4; b++) {
            if (i + b * 8 < deg) {               // warp-uniform guard
                #pragma unroll
                for (int j = b * 8; j < b * 8 + 8; j++) {
                    int src = __shfl_sync(0xffffffffu, s, j);
                    float p = __shfl_sync(0xffffffffu, pe[j & 3], h8 + (j >> 2));
                    unsigned raw = g_h1f8[src * 32 + lane];
                    __half2_raw lo = __nv_cvt_fp8x2_to_halfraw2(
                        (__nv_fp8x2_storage_t)(raw & 0xFFFFu), __NV_E4M3);
                    __half2_raw hi = __nv_cvt_fp8x2_to_halfraw2(
                        (__nv_fp8x2_storage_t)(raw >> 16), __NV_E4M3);
                    __half2 ph = __float2half2_rn(p);
                    acc01 = __hfma2(ph, *reinterpret_cast<__half2*>(&lo), acc01);
                    acc23 = __hfma2(ph, *reinterpret_cast<__half2*>(&hi), acc23);
                }
            }
        }
    }

    #pragma unroll
    for (int o = 1; o < 8; o <<= 1)
        psum += __shfl_xor_sync(0xffffffffu, psum, o);

    float inv = 1.0f / psum;
    float2 f01 = __half22float2(acc01);
    float2 f23 = __half22float2(acc23);
    float4 o;
    o.x = f01.x * inv; o.y = f01.y * inv;
    o.z = f23.x * inv; o.w = f23.y * inv;
    reinterpret_cast<float4*>(g_out1)[gw * 32 + lane] = o;
}

// ---------------- K3: bias+ELU, GEMM2 in half2, attn coeffs -----------------
__global__ void __launch_bounds__(256) k_node1(
        const float* __restrict__ W2, const float* __restrict__ b1,
        const float* __restrict__ attS2, const float* __restrict__ attD2, int n) {
    int tx = threadIdx.x;        // col 0..31
    int ty = threadIdx.y;        // k-chunk 0..7 (16 k each)
    int t = ty * 32 + tx;

    // W2 k-pairs in half2 registers: w2r[j] = (W2[ty*16+2j][tx], W2[ty*16+2j+1][tx])
    __half2 w2r[8];
    #pragma unroll
    for (int j = 0; j < 8; j++) {
        float lo = W2[(ty * 16 + 2 * j) * C2 + tx];
        float hi = W2[(ty * 16 + 2 * j + 1) * C2 + tx];
        w2r[j] = __floats2half2_rn(lo, hi);
    }

    __shared__ __half2 hsh2[16 * 64];   // 16 nodes x 128 ch (half2 pairs), 2 KB
    __shared__ float ps[8][16][32];     // 16 KB partials

    int n0 = blockIdx.x * 16;
    {
        // each thread: 8 consecutive channels (4 half2) of one node
        int nn = t >> 4;
        int k8 = (t & 15) * 8;          // channel offset 0..120
        int node = n0 + nn;
        float v[8];
        if (node < n) {
            const float4* o4 = reinterpret_cast<const float4*>(g_out1) + node * 32 + (k8 >> 2);
            const float4* b4 = reinterpret_cast<const float4*>(b1) + (k8 >> 2);
            float4 va = o4[0], vb = o4[1];
            float4 ba = b4[0], bb = b4[1];
            v[0] = va.x + ba.x; v[1] = va.y + ba.y; v[2] = va.z + ba.z; v[3] = va.w + ba.w;
            v[4] = vb.x + bb.x; v[5] = vb.y + bb.y; v[6] = vb.z + bb.z; v[7] = vb.w + bb.w;
            #pragma unroll
            for (int j = 0; j < 8; j++) v[j] = v[j] > 0.f ? v[j] : expm1f(v[j]);
        } else {
            #pragma unroll
            for (int j = 0; j < 8; j++) v[j] = 0.f;
        }
        #pragma unroll
        for (int j = 0; j < 4; j++)
            hsh2[nn * 64 + (k8 >> 1) + j] = __floats2half2_rn(v[2 * j], v[2 * j + 1]);
    }
    __syncthreads();

    for (int nn = 0; nn < 16; nn++) {
        const uint4* hp = reinterpret_cast<const uint4*>(hsh2 + nn * 64);
        uint4 A = hp[ty * 2], B = hp[ty * 2 + 1];   // 8 half2 (16 k), broadcast
        __half2 acc = __float2half2_rn(0.f);
        acc = __hfma2(*reinterpret_cast<__half2*>(&A.x), w2r[0], acc);
        acc = __hfma2(*reinterpret_cast<__half2*>(&A.y), w2r[1], acc);
        acc = __hfma2(*reinterpret_cast<__half2*>(&A.z), w2r[2], acc);
        acc = __hfma2(*reinterpret_cast<__half2*>(&A.w), w2r[3], acc);
        acc = __hfma2(*reinterpret_cast<__half2*>(&B.x), w2r[4], acc);
        acc = __hfma2(*reinterpret_cast<__half2*>(&B.y), w2r[5], acc);
        acc = __hfma2(*reinterpret_cast<__half2*>(&B.z), w2r[6], acc);
        acc = __hfma2(*reinterpret_cast<__half2*>(&B.w), w2r[7], acc);
        float2 f = __half22float2(acc);
        ps[ty][nn][tx] = f.x + f.y;
    }
    __syncthreads();

    float aS = attS2[tx], aD = attD2[tx];
    #pragma unroll
    for (int pp = 0; pp < 2; pp++) {
        int nn = pp * 8 + (t >> 5);
        int col = tx;
        float s = 0.f;
        #pragma unroll
        for (int j = 0; j < 8; j++) s += ps[j][nn][col];
        int node = n0 + nn;
        float vs = s * aS, vd = s * aD;
        #pragma unroll
        for (int o = 16; o > 0; o >>= 1) {
            vs += __shfl_down_sync(0xffffffffu, vs, o);
            vd += __shfl_down_sync(0xffffffffu, vd, o);
        }
        if (node < n) {
            g_h2h[node * C2 + col] = __float2half(s);
            if (col == 0) { g_asrc2[node] = vs; g_adst2[node] = vd; }
        }
    }
}

// ---------------- K4: edge pass 2 + fused global-sum + cursor reset ---------
__global__ void k_edge2(int n) {
    __shared__ float sblock[C2];
    int t = threadIdx.x;
    if (t < C2) sblock[t] = 0.f;
    __syncthreads();

    int gw = (blockIdx.x * blockDim.x + t) >> 5;
    int lane = t & 31;
    if (gw < n) {
        int g = lane >> 3, l8 = lane & 7;
        float aD = g_adst2[gw];
        int start = gw * SLOTS, deg = g_cursor[gw];

        const uint2* h2v = reinterpret_cast<const uint2*>(g_h2h);
        float4 acc = make_float4(0.f, 0.f, 0.f, 0.f);
        float psum = 0.f;

        // self-loop in-register (group 0 only; reduce spreads it)
        if (g == 0) {
            float eS = g_asrc2[gw] + aD;
            eS = fmaxf(eS, 0.2f * eS);
            float pS = __expf(eS);
            uint2 raw = h2v[gw * 8 + l8];
            float2 f01 = __half22float2(*reinterpret_cast<__half2*>(&raw.x));
            float2 f23 = __half22float2(*reinterpret_cast<__half2*>(&raw.y));
            acc.x += pS * f01.x; acc.y += pS * f01.y;
            acc.z += pS * f23.x; acc.w += pS * f23.y;
            psum += pS;
        }

        #pragma unroll 4
        for (int i = g; i < deg; i += 4) {
            int src = g_sortbuf[start + i];
            float e = g_asrc2[src] + aD;
            e = fmaxf(e, 0.2f * e);
            float p = __expf(e);
            uint2 raw = h2v[src * 8 + l8];
            float2 f01 = __half22float2(*reinterpret_cast<__half2*>(&raw.x));
            float2 f23 = __half22float2(*reinterpret_cast<__half2*>(&raw.y));
            acc.x += p * f01.x; acc.y += p * f01.y;
            acc.z += p * f23.x; acc.w += p * f23.y;
            psum += p;
        }
        #pragma unroll
        for (int o = 8; o <= 16; o <<= 1) {
            acc.x += __shfl_xor_sync(0xffffffffu, acc.x, o);
            acc.y += __shfl_xor_sync(0xffffffffu, acc.y, o);
            acc.z += __shfl_xor_sync(0xffffffffu, acc.z, o);
            acc.w += __shfl_xor_sync(0xffffffffu, acc.w, o);
            psum  += __shfl_xor_sync(0xffffffffu, psum,  o);
        }
        if (lane < 8) {
            float inv = 1.0f / psum;
            int c = lane * 4;
            atomicAdd(&sblock[c + 0], acc.x * inv);
            atomicAdd(&sblock[c + 1], acc.y * inv);
            atomicAdd(&sblock[c + 2], acc.z * inv);
            atomicAdd(&sblock[c + 3], acc.w * inv);
        }
        if (lane == 0) g_cursor[gw] = 0;   // restore invariant for next replay
    }
    __syncthreads();
    if (t < C2)
        atomicAdd(&g_paccum[(blockIdx.x & (PB - 1)) * C2 + t], sblock[t]);
}

// ---------------- K5: partials -> mean -> logits -> softmax; zero paccum ----
__global__ void k_out(const float* __restrict__ b2,
                      const float* __restrict__ linW, const float* __restrict__ linb,
                      float* __restrict__ out, int n) {
    __shared__ float part[4][C2];
    __shared__ float tot[C2];
    int t = threadIdx.x;      // 128 threads
    int c = t & 31, q = t >> 5;
    float s = 0.f;
    #pragma unroll
    for (int b = 0; b < PB / 4; b++)
        s += g_paccum[(q * (PB / 4) + b) * C2 + c];
    part[q][c] = s;
    __syncthreads();
    // restore invariant: zero paccum for next replay (all reads are done)
    for (int i = t; i < PB * C2; i += 128) g_paccum[i] = 0.f;
    if (t < C2) {
        float v = (part[0][t] + part[1][t]) + (part[2][t] + part[3][t]);
        tot[t] = v / (float)n + b2[t];
    }
    __syncthreads();
    if (t == 0) {
        float logits[CLS];
        for (int j = 0; j < CLS; j++) {
            float acc = linb[j];
            for (int cc = 0; cc < C2; cc++)
                acc += tot[cc] * linW[cc * CLS + j];
            logits[j] = acc;
        }
        float m = fmaxf(logits[0], fmaxf(logits[1], logits[2]));
        float e0 = expf(logits[0] - m);
        float e1 = expf(logits[1] - m);
        float e2 = expf(logits[2] - m);
        float sm = e0 + e1 + e2;
        out[0] = e0 / sm; out[1] = e1 / sm; out[2] = e2 / sm;
    }
}

// ---------------- launcher ---------------------------------------------------
extern "C" void kernel_launch(void* const* d_in, const int* in_sizes, int n_in,
                              void* d_out, int out_size) {
    const float* x        = (const float*)d_in[0];
    const float* W1       = (const float*)d_in[1];
    const float* att_src1 = (const float*)d_in[2];
    const float* att_dst1 = (const float*)d_in[3];
    const float* b1       = (const float*)d_in[4];
    const float* W2       = (const float*)d_in[5];
    const float* att_src2 = (const float*)d_in[6];
    const float* att_dst2 = (const float*)d_in[7];
    const float* b2       = (const float*)d_in[8];
    const float* linW     = (const float*)d_in[9];
    const float* linb     = (const float*)d_in[10];
    const int*   ei       = (const int*)d_in[11];

    int n  = in_sizes[0] / F_IN;       // 50000
    int E  = in_sizes[11] / 2;         // 800000
    float* out = (float*)d_out;

    int nGemm = (n + 63) / 64;                   // 782
    int nScat = (E + 1023) / 1024;               // 782
    k_gemm1_scatter<<<nGemm + nScat, 128>>>(x, W1, att_src1, att_dst1,
                                            ei, n, E, nGemm);

    {
        long long threads = (long long)n * 32;
        k_edge1<<<(int)((threads + 255) / 256), 256>>>(n);
    }

    k_node1<<<(n + 15) / 16, dim3(32, 8)>>>(W2, b1, att_src2, att_dst2, n);

    {
        long long threads = (long long)n * 32;
        k_edge2<<<(int)((threads + 255) / 256), 256>>>(n);
    }

    k_out<<<1, 128>>>(b2, linW, linb, out, n);
}